// round 10
// baseline (speedup 1.0000x reference)
#include <cuda_runtime.h>
#include <cuda_bf16.h>
#include <cstdint>

#define B_ROWS 8192
#define P_DIM 512
#define C_CLASSES 1000
#define C_PAD 1024

#define BM 128
#define BN 128
#define BK 64
#define NCHUNK (P_DIM / BK)   // 8
#define NSTAGE 3
#define LDA 72                 // BK + 8 pad: 144B row stride, conflict-free LDSM
#define LDB 72

#define A_STAGE_BYTES (BM * LDA * 2)   // 18432
#define B_STAGE_BYTES (BN * LDB * 2)   // 18432
#define STAGE_BYTES (A_STAGE_BYTES + B_STAGE_BYTES)   // 36864
#define SMEM_TOTAL (NSTAGE * STAGE_BYTES + 16)        // 110608 -> 2 CTAs/SM

#define GRID_CTAS 296          // 148 SMs * 2 CTAs

// work units: [0,128) means-prep, [128,1152) x-prep, [1152,1664) gemm tiles
#define U_MEANS 128
#define U_X (U_MEANS + B_ROWS / 8)     // 1152
#define U_END (U_X + 512)              // 1664

// ---- scratch ----
__device__ __nv_bfloat16 g_xb[B_ROWS * P_DIM];
__device__ __nv_bfloat16 g_mb[C_PAD * P_DIM];
__device__ float g_fx[B_ROWS];     // 2 * r_b
__device__ float g_xsq[B_ROWS];
__device__ float g_msq[C_PAD];
// sync block (one memset): [0]=ctr, [1..8]=mdone per nblk, [16..79]=xdone per mblk
__device__ unsigned g_sync[80];

// ======================= PTX helpers =======================
__device__ __forceinline__ uint32_t smem_u32(const void* p) {
    uint32_t a;
    asm("{ .reg .u64 t; cvta.to.shared.u64 t, %1; cvt.u32.u64 %0, t; }" : "=r"(a) : "l"(p));
    return a;
}
__device__ __forceinline__ void cp_async16(uint32_t dst, const void* src) {
    asm volatile("cp.async.cg.shared.global [%0], [%1], 16;" :: "r"(dst), "l"(src) : "memory");
}
__device__ __forceinline__ void cp_commit() {
    asm volatile("cp.async.commit_group;" ::: "memory");
}
__device__ __forceinline__ void cp_wait1() {
    asm volatile("cp.async.wait_group 1;" ::: "memory");
}
__device__ __forceinline__ void cp_wait0() {
    asm volatile("cp.async.wait_group 0;" ::: "memory");
}
__device__ __forceinline__ void ldsm_x4(uint32_t& r0, uint32_t& r1, uint32_t& r2, uint32_t& r3,
                                        uint32_t addr) {
    asm volatile("ldmatrix.sync.aligned.m8n8.x4.shared.b16 {%0,%1,%2,%3}, [%4];"
                 : "=r"(r0), "=r"(r1), "=r"(r2), "=r"(r3) : "r"(addr));
}
__device__ __forceinline__ void mma16816(float c[4], const uint32_t a[4], const uint32_t b[2]) {
    asm volatile(
        "mma.sync.aligned.m16n8k16.row.col.f32.bf16.bf16.f32 "
        "{%0,%1,%2,%3}, {%4,%5,%6,%7}, {%8,%9}, {%0,%1,%2,%3};\n"
        : "+f"(c[0]), "+f"(c[1]), "+f"(c[2]), "+f"(c[3])
        : "r"(a[0]), "r"(a[1]), "r"(a[2]), "r"(a[3]), "r"(b[0]), "r"(b[1]));
}
__device__ __forceinline__ unsigned ld_acq(const unsigned* p) {
    unsigned v;
    asm volatile("ld.acquire.gpu.u32 %0, [%1];" : "=r"(v) : "l"(p) : "memory");
    return v;
}

// ======================= prep unit bodies (8 warps, warp per row) =======================
__device__ __forceinline__ void do_means_unit(int u, const float* __restrict__ means) {
    const int wid = threadIdx.x >> 5, lane = threadIdx.x & 31;
    const int c = u * 8 + wid;
    float4 v[4];
    float ss = 0.0f;
    if (c < C_CLASSES) {
        const float4* src = (const float4*)(means + (size_t)c * P_DIM);
        #pragma unroll
        for (int i = 0; i < 4; i++) {
            v[i] = src[lane + i * 32];
            ss += v[i].x * v[i].x + v[i].y * v[i].y + v[i].z * v[i].z + v[i].w * v[i].w;
        }
    } else {
        #pragma unroll
        for (int i = 0; i < 4; i++) v[i] = make_float4(0.f, 0.f, 0.f, 0.f);
    }
    #pragma unroll
    for (int o = 16; o > 0; o >>= 1) ss += __shfl_xor_sync(0xffffffffu, ss, o);

    uint2* dst = (uint2*)(g_mb + (size_t)c * P_DIM);
    #pragma unroll
    for (int i = 0; i < 4; i++) {
        __nv_bfloat162 lo = __floats2bfloat162_rn(v[i].x, v[i].y);
        __nv_bfloat162 hi = __floats2bfloat162_rn(v[i].z, v[i].w);
        uint2 p; p.x = *(uint32_t*)&lo; p.y = *(uint32_t*)&hi;
        dst[lane + i * 32] = p;
    }
    if (lane == 0) g_msq[c] = ss;
    __syncthreads();
    if (threadIdx.x == 0) {
        __threadfence();
        atomicAdd(&g_sync[1 + (u >> 4)], 1u);    // nblk done count
    }
}

__device__ __forceinline__ void do_x_unit(int w, const float* __restrict__ x,
                                          const float* __restrict__ means) {
    const int wid = threadIdx.x >> 5, lane = threadIdx.x & 31;
    const int b = w * 8 + wid;
    float sc = 0.0f;
    {
        const float4* m0 = (const float4*)means;
        #pragma unroll
        for (int i = 0; i < 4; i++) {
            float4 m = m0[lane + i * 32];
            sc += m.x * m.x + m.y * m.y + m.z * m.z + m.w * m.w;
        }
        #pragma unroll
        for (int o = 16; o > 0; o >>= 1) sc += __shfl_xor_sync(0xffffffffu, sc, o);
        sc = sqrtf(sc);
    }
    const float4* src = (const float4*)(x + (size_t)b * P_DIM);
    float4 v[4];
    float ss = 0.0f;
    #pragma unroll
    for (int i = 0; i < 4; i++) {
        v[i] = src[lane + i * 32];
        ss += v[i].x * v[i].x + v[i].y * v[i].y + v[i].z * v[i].z + v[i].w * v[i].w;
    }
    #pragma unroll
    for (int o = 16; o > 0; o >>= 1) ss += __shfl_xor_sync(0xffffffffu, ss, o);

    uint2* dst = (uint2*)(g_xb + (size_t)b * P_DIM);
    #pragma unroll
    for (int i = 0; i < 4; i++) {
        __nv_bfloat162 lo = __floats2bfloat162_rn(v[i].x, v[i].y);
        __nv_bfloat162 hi = __floats2bfloat162_rn(v[i].z, v[i].w);
        uint2 p; p.x = *(uint32_t*)&lo; p.y = *(uint32_t*)&hi;
        dst[lane + i * 32] = p;
    }
    if (lane == 0) {
        float norm = sqrtf(ss);
        float r = sc / (norm + 1e-10f);
        g_fx[b] = 2.0f * r;
        float tn = norm * r;
        g_xsq[b] = tn * tn;
    }
    __syncthreads();
    if (threadIdx.x == 0) {
        __threadfence();
        atomicAdd(&g_sync[16 + (w >> 4)], 1u);   // mblk done count
    }
}

// ======================= fused persistent kernel =======================
__global__ __launch_bounds__(256, 2) void gemm_fused(float* __restrict__ out,
                                                     const float* __restrict__ x,
                                                     const float* __restrict__ means) {
    extern __shared__ __align__(16) char smem_raw[];
    const uint32_t sbase = smem_u32(smem_raw);
    unsigned* u_bcast = (unsigned*)(smem_raw + NSTAGE * STAGE_BYTES);

    const int t = threadIdx.x;
    const int warp = t >> 5, lane = t & 31;
    const int wm = warp & 3;
    const int wn = warp >> 2;
    const int grp = lane >> 2, tid4 = lane & 3;

    // tile-invariant cp.async mapping
    uint32_t src_inv[8];
    uint32_t dsts[8];
    #pragma unroll
    for (int i = 0; i < 8; i++) {
        int v = t + i * 256;
        int v2 = v & 1023;
        int r = v2 >> 3, cc = (v2 & 7) * 8;
        src_inv[i] = (uint32_t)(r * P_DIM + cc);
        dsts[i] = (uint32_t)(r * (i < 4 ? LDA : LDB) + cc) * 2 + (i < 4 ? 0u : (uint32_t)A_STAGE_BYTES);
    }
    const int lq = lane >> 3, lr = lane & 7;
    const uint32_t a_lane_off =
        (uint32_t)((wm * 32 + (lq & 1) * 8 + lr) * LDA + (lq >> 1) * 8) * 2;
    const uint32_t b_lane_off =
        A_STAGE_BYTES + (uint32_t)((wn * 64 + (lq >> 1) * 8 + lr) * LDB + (lq & 1) * 8) * 2;

    for (;;) {
        if (t == 0) *u_bcast = atomicAdd(&g_sync[0], 1u);
        __syncthreads();
        const unsigned u = *u_bcast;
        if (u >= U_END) break;

        if (u < U_MEANS) { do_means_unit((int)u, means); continue; }
        if (u < U_X)     { do_x_unit((int)(u - U_MEANS), x, means); continue; }

        const unsigned tile = u - U_X;
        const int mblk = (int)(tile >> 3);
        const int nblk = (int)(tile & 7);
        const int bm = mblk * BM;
        const int bn = nblk * BN;

        // wait for prep of this tile's row/col blocks
        if (t == 0) {
            while (ld_acq(&g_sync[16 + mblk]) < 16u || ld_acq(&g_sync[1 + nblk]) < 16u)
                __nanosleep(64);
        }
        __syncthreads();

        const __nv_bfloat16* abase = g_xb + (size_t)bm * P_DIM;
        const __nv_bfloat16* bbase = g_mb + (size_t)bn * P_DIM;

        float acc[2][8][4];
        #pragma unroll
        for (int mi = 0; mi < 2; mi++)
            #pragma unroll
            for (int ni = 0; ni < 8; ni++)
                #pragma unroll
                for (int q = 0; q < 4; q++) acc[mi][ni][q] = 0.0f;

        auto issue_stage = [&](int c) {
            const uint32_t st = sbase + (c % NSTAGE) * STAGE_BYTES;
            const int koff = c * BK;
            #pragma unroll
            for (int i = 0; i < 8; i++)
                cp_async16(st + dsts[i], (i < 4 ? abase : bbase) + src_inv[i] + koff);
        };

        issue_stage(0); cp_commit();
        issue_stage(1); cp_commit();

        #pragma unroll 1
        for (int c = 0; c < NCHUNK; c++) {
            if (c == NCHUNK - 1) cp_wait0(); else cp_wait1();
            __syncthreads();

            if (c + 2 < NCHUNK) { issue_stage(c + 2); cp_commit(); }

            const uint32_t st = sbase + (c % NSTAGE) * STAGE_BYTES;
            const uint32_t ast = st + a_lane_off;
            const uint32_t bst = st + b_lane_off;

            #pragma unroll
            for (int kk = 0; kk < BK; kk += 16) {
                uint32_t a[2][4];
                #pragma unroll
                for (int mi = 0; mi < 2; mi++)
                    ldsm_x4(a[mi][0], a[mi][1], a[mi][2], a[mi][3],
                            ast + (uint32_t)(mi * 16 * LDA + kk) * 2);
                uint32_t b[8][2];
                #pragma unroll
                for (int ng = 0; ng < 4; ng++)
                    ldsm_x4(b[ng * 2][0], b[ng * 2][1], b[ng * 2 + 1][0], b[ng * 2 + 1][1],
                            bst + (uint32_t)(ng * 16 * LDB + kk) * 2);
                #pragma unroll
                for (int mi = 0; mi < 2; mi++)
                    #pragma unroll
                    for (int ni = 0; ni < 8; ni++)
                        mma16816(acc[mi][ni], a[mi], b[ni]);
            }
        }

        // fused epilogue: out = fx_b * cross - xsq_b - msq_c
        #pragma unroll
        for (int mi = 0; mi < 2; mi++) {
            int row0 = bm + wm * 32 + mi * 16 + grp;
            float f0 = g_fx[row0], xs0 = g_xsq[row0];
            float f1 = g_fx[row0 + 8], xs1 = g_xsq[row0 + 8];
            #pragma unroll
            for (int ni = 0; ni < 8; ni++) {
                int col = bn + wn * 64 + ni * 8 + tid4 * 2;
                if (col < C_CLASSES) {
                    float ms = g_msq[col];
                    out[(size_t)row0 * C_CLASSES + col]       = f0 * acc[mi][ni][0] - xs0 - ms;
                    out[(size_t)(row0 + 8) * C_CLASSES + col] = f1 * acc[mi][ni][2] - xs1 - ms;
                }
                if (col + 1 < C_CLASSES) {
                    float ms = g_msq[col + 1];
                    out[(size_t)row0 * C_CLASSES + col + 1]       = f0 * acc[mi][ni][1] - xs0 - ms;
                    out[(size_t)(row0 + 8) * C_CLASSES + col + 1] = f1 * acc[mi][ni][3] - xs1 - ms;
                }
            }
        }
    }
}

extern "C" void kernel_launch(void* const* d_in, const int* in_sizes, int n_in,
                              void* d_out, int out_size) {
    const float* x = (const float*)d_in[0];      // (8192, 512)
    const float* means = (const float*)d_in[1];  // (1000, 512)
    float* out = (float*)d_out;                  // (8192, 1000)
    (void)in_sizes; (void)n_in; (void)out_size;

    static void* sync_addr = nullptr;
    static int smem_set = 0;
    if (!smem_set) {
        cudaFuncSetAttribute(gemm_fused, cudaFuncAttributeMaxDynamicSharedMemorySize, SMEM_TOTAL);
        cudaGetSymbolAddress(&sync_addr, g_sync);
        smem_set = 1;
    }

    cudaMemsetAsync(sync_addr, 0, 80 * sizeof(unsigned), 0);
    gemm_fused<<<GRID_CTAS, 256, SMEM_TOTAL>>>(out, x, means);
}

// round 11
// speedup vs baseline: 1.2434x; 1.2434x over previous
#include <cuda_runtime.h>
#include <cuda_fp16.h>
#include <cstdint>

#define B_ROWS 8192
#define P_DIM 512
#define C_CLASSES 1000
#define C_PAD 1024

#define BM 128
#define BN 128
#define BK 64
#define NCHUNK (P_DIM / BK)   // 8
#define NSTAGE 2
#define LDA 72                 // elements; 144B row stride, conflict-free LDSM
#define LDB 72

#define A_STAGE_BYTES (BM * LDA * 2)   // 18432
#define B_STAGE_BYTES (BN * LDB * 2)   // 18432
#define STAGE_BYTES (A_STAGE_BYTES + B_STAGE_BYTES)   // 36864
#define SMEM_TOTAL (NSTAGE * STAGE_BYTES)             // 73728 -> 3 CTAs/SM

// ---- scratch ----
__device__ __half g_xh[B_ROWS * P_DIM];
__device__ __half g_mh[C_PAD * P_DIM];
__device__ float g_fx[B_ROWS];     // 2 * r_b
__device__ float g_xsq[B_ROWS];
__device__ float g_msq[C_PAD];

// ======================= PTX helpers =======================
__device__ __forceinline__ uint32_t smem_u32(const void* p) {
    uint32_t a;
    asm("{ .reg .u64 t; cvta.to.shared.u64 t, %1; cvt.u32.u64 %0, t; }" : "=r"(a) : "l"(p));
    return a;
}
__device__ __forceinline__ void cp_async16(uint32_t dst, const void* src) {
    asm volatile("cp.async.cg.shared.global [%0], [%1], 16;" :: "r"(dst), "l"(src) : "memory");
}
__device__ __forceinline__ void cp_commit() {
    asm volatile("cp.async.commit_group;" ::: "memory");
}
__device__ __forceinline__ void cp_wait0() {
    asm volatile("cp.async.wait_group 0;" ::: "memory");
}
__device__ __forceinline__ void ldsm_x4(uint32_t& r0, uint32_t& r1, uint32_t& r2, uint32_t& r3,
                                        uint32_t addr) {
    asm volatile("ldmatrix.sync.aligned.m8n8.x4.shared.b16 {%0,%1,%2,%3}, [%4];"
                 : "=r"(r0), "=r"(r1), "=r"(r2), "=r"(r3) : "r"(addr));
}
// fp16 x fp16 -> fp16 accum
__device__ __forceinline__ void mma16816h(uint32_t c[2], const uint32_t a[4], const uint32_t b[2]) {
    asm volatile(
        "mma.sync.aligned.m16n8k16.row.col.f16.f16.f16.f16 "
        "{%0,%1}, {%2,%3,%4,%5}, {%6,%7}, {%0,%1};\n"
        : "+r"(c[0]), "+r"(c[1])
        : "r"(a[0]), "r"(a[1]), "r"(a[2]), "r"(a[3]), "r"(b[0]), "r"(b[1]));
}

// ======================= fused prep kernel =======================
// blocks [0,128): class rows (8/block). blocks [128,1152): x rows (8/block).
__global__ void prep_all(const float* __restrict__ x, const float* __restrict__ means) {
    const int wid = threadIdx.x >> 5, lane = threadIdx.x & 31;

    if (blockIdx.x < 128) {
        const int c = blockIdx.x * 8 + wid;
        float4 v[4];
        float ss = 0.0f;
        if (c < C_CLASSES) {
            const float4* src = (const float4*)(means + (size_t)c * P_DIM);
            #pragma unroll
            for (int i = 0; i < 4; i++) {
                v[i] = src[lane + i * 32];
                ss += v[i].x * v[i].x + v[i].y * v[i].y + v[i].z * v[i].z + v[i].w * v[i].w;
            }
        } else {
            #pragma unroll
            for (int i = 0; i < 4; i++) v[i] = make_float4(0.f, 0.f, 0.f, 0.f);
        }
        #pragma unroll
        for (int o = 16; o > 0; o >>= 1) ss += __shfl_xor_sync(0xffffffffu, ss, o);

        uint2* dst = (uint2*)(g_mh + (size_t)c * P_DIM);
        #pragma unroll
        for (int i = 0; i < 4; i++) {
            __half2 lo = __floats2half2_rn(v[i].x, v[i].y);
            __half2 hi = __floats2half2_rn(v[i].z, v[i].w);
            uint2 p; p.x = *(uint32_t*)&lo; p.y = *(uint32_t*)&hi;
            dst[lane + i * 32] = p;
        }
        if (lane == 0) g_msq[c] = ss;
    } else {
        const int b = (blockIdx.x - 128) * 8 + wid;
        float sc = 0.0f;
        {
            const float4* m0 = (const float4*)means;
            #pragma unroll
            for (int i = 0; i < 4; i++) {
                float4 m = m0[lane + i * 32];
                sc += m.x * m.x + m.y * m.y + m.z * m.z + m.w * m.w;
            }
            #pragma unroll
            for (int o = 16; o > 0; o >>= 1) sc += __shfl_xor_sync(0xffffffffu, sc, o);
            sc = sqrtf(sc);
        }

        const float4* src = (const float4*)(x + (size_t)b * P_DIM);
        float4 v[4];
        float ss = 0.0f;
        #pragma unroll
        for (int i = 0; i < 4; i++) {
            v[i] = src[lane + i * 32];
            ss += v[i].x * v[i].x + v[i].y * v[i].y + v[i].z * v[i].z + v[i].w * v[i].w;
        }
        #pragma unroll
        for (int o = 16; o > 0; o >>= 1) ss += __shfl_xor_sync(0xffffffffu, ss, o);

        uint2* dst = (uint2*)(g_xh + (size_t)b * P_DIM);
        #pragma unroll
        for (int i = 0; i < 4; i++) {
            __half2 lo = __floats2half2_rn(v[i].x, v[i].y);
            __half2 hi = __floats2half2_rn(v[i].z, v[i].w);
            uint2 p; p.x = *(uint32_t*)&lo; p.y = *(uint32_t*)&hi;
            dst[lane + i * 32] = p;
        }
        if (lane == 0) {
            float norm = sqrtf(ss);
            float r = sc / (norm + 1e-10f);
            g_fx[b] = 2.0f * r;
            float tn = norm * r;
            g_xsq[b] = tn * tn;
        }
    }
}

// ======================= fp16 HMMA GEMM, 3 CTAs/SM =======================
// grid (8, 64), 256 threads = 8 warps, 4(m) x 2(n), warptile 32x64.
// fp16 accumulators keep regs <= 84 so 3 CTAs (24 warps) fit per SM.
__global__ __launch_bounds__(256, 3) void gemm_logits(float* __restrict__ out) {
    extern __shared__ __align__(16) char smem_raw[];
    const uint32_t sbase = smem_u32(smem_raw);

    const int t = threadIdx.x;
    const int warp = t >> 5, lane = t & 31;
    const int wm = warp & 3;    // m-warp 0..3
    const int wn = warp >> 2;   // n-warp 0..1
    const int grp = lane >> 2, tid4 = lane & 3;
    const int bm = blockIdx.y * BM;
    const int bn = blockIdx.x * BN;

    // cp.async mapping: A = 1024 16B-chunks, B = 1024; 8 per thread.
    const __half* abase = g_xh + (size_t)bm * P_DIM;
    const __half* bbase = g_mh + (size_t)bn * P_DIM;
    uint32_t src_inv[8];
    uint32_t dsts[8];
    #pragma unroll
    for (int i = 0; i < 8; i++) {
        int v = t + i * 256;
        int v2 = v & 1023;
        int r = v2 >> 3, cc = (v2 & 7) * 8;
        src_inv[i] = (uint32_t)(r * P_DIM + cc);
        dsts[i] = (uint32_t)(r * (i < 4 ? LDA : LDB) + cc) * 2 + (i < 4 ? 0u : (uint32_t)A_STAGE_BYTES);
    }

    // LDSM lane addressing
    const int lq = lane >> 3, lr = lane & 7;
    const uint32_t a_lane_off =
        (uint32_t)((wm * 32 + (lq & 1) * 8 + lr) * LDA + (lq >> 1) * 8) * 2;
    const uint32_t b_lane_off =
        A_STAGE_BYTES + (uint32_t)((wn * 64 + (lq >> 1) * 8 + lr) * LDB + (lq & 1) * 8) * 2;

    uint32_t acc[2][8][2];   // packed f16x2 accumulators
    #pragma unroll
    for (int mi = 0; mi < 2; mi++)
        #pragma unroll
        for (int ni = 0; ni < 8; ni++) {
            acc[mi][ni][0] = 0u;
            acc[mi][ni][1] = 0u;
        }

    auto issue_stage = [&](int c) {
        const uint32_t st = sbase + (c & 1) * STAGE_BYTES;
        const int koff = c * BK;
        #pragma unroll
        for (int i = 0; i < 8; i++)
            cp_async16(st + dsts[i], (i < 4 ? abase : bbase) + src_inv[i] + koff);
    };

    issue_stage(0); cp_commit();

    #pragma unroll 1
    for (int c = 0; c < NCHUNK; c++) {
        cp_wait0();          // stage c landed
        __syncthreads();     // all warps done reading stage c-1 (same buffer as c+1)

        if (c + 1 < NCHUNK) { issue_stage(c + 1); cp_commit(); }

        const uint32_t st = sbase + (c & 1) * STAGE_BYTES;
        const uint32_t ast = st + a_lane_off;
        const uint32_t bst = st + b_lane_off;

        #pragma unroll
        for (int kk = 0; kk < BK; kk += 16) {
            uint32_t a[2][4];
            #pragma unroll
            for (int mi = 0; mi < 2; mi++)
                ldsm_x4(a[mi][0], a[mi][1], a[mi][2], a[mi][3],
                        ast + (uint32_t)(mi * 16 * LDA + kk) * 2);
            uint32_t b[8][2];
            #pragma unroll
            for (int ng = 0; ng < 4; ng++)
                ldsm_x4(b[ng * 2][0], b[ng * 2][1], b[ng * 2 + 1][0], b[ng * 2 + 1][1],
                        bst + (uint32_t)(ng * 16 * LDB + kk) * 2);
            #pragma unroll
            for (int mi = 0; mi < 2; mi++)
                #pragma unroll
                for (int ni = 0; ni < 8; ni++)
                    mma16816h(acc[mi][ni], a[mi], b[ni]);
        }
        __syncthreads();     // done reading stage c before c+2 overwrites (next iter top handles via wait; this guards warp skew)
    }

    // ---- fused epilogue: out = fx_b * cross - xsq_b - msq_c ----
    #pragma unroll
    for (int mi = 0; mi < 2; mi++) {
        int row0 = bm + wm * 32 + mi * 16 + grp;
        float f0 = g_fx[row0], xs0 = g_xsq[row0];
        float f1 = g_fx[row0 + 8], xs1 = g_xsq[row0 + 8];
        #pragma unroll
        for (int ni = 0; ni < 8; ni++) {
            int col = bn + wn * 64 + ni * 8 + tid4 * 2;
            __half2 h0 = *(__half2*)&acc[mi][ni][0];
            __half2 h1 = *(__half2*)&acc[mi][ni][1];
            float2 c0 = __half22float2(h0);
            float2 c1 = __half22float2(h1);
            if (col < C_CLASSES) {
                float ms = g_msq[col];
                out[(size_t)row0 * C_CLASSES + col]       = f0 * c0.x - xs0 - ms;
                out[(size_t)(row0 + 8) * C_CLASSES + col] = f1 * c1.x - xs1 - ms;
            }
            if (col + 1 < C_CLASSES) {
                float ms = g_msq[col + 1];
                out[(size_t)row0 * C_CLASSES + col + 1]       = f0 * c0.y - xs0 - ms;
                out[(size_t)(row0 + 8) * C_CLASSES + col + 1] = f1 * c1.y - xs1 - ms;
            }
        }
    }
}

extern "C" void kernel_launch(void* const* d_in, const int* in_sizes, int n_in,
                              void* d_out, int out_size) {
    const float* x = (const float*)d_in[0];      // (8192, 512)
    const float* means = (const float*)d_in[1];  // (1000, 512)
    float* out = (float*)d_out;                  // (8192, 1000)
    (void)in_sizes; (void)n_in; (void)out_size;

    static int smem_set = 0;
    if (!smem_set) {
        cudaFuncSetAttribute(gemm_logits, cudaFuncAttributeMaxDynamicSharedMemorySize, SMEM_TOTAL);
        smem_set = 1;
    }

    prep_all<<<128 + B_ROWS / 8, 256>>>(x, means);
    dim3 grid(C_PAD / BN, B_ROWS / BM);
    gemm_logits<<<grid, 256, SMEM_TOTAL>>>(out);
}

// round 12
// speedup vs baseline: 1.2507x; 1.0059x over previous
#include <cuda_runtime.h>
#include <cuda_fp16.h>
#include <cstdint>

#define B_ROWS 8192
#define P_DIM 512
#define C_CLASSES 1000
#define C_PAD 1024

#define BM 128
#define BN 128
#define BK 32
#define NCHUNK (P_DIM / BK)   // 16
#define NSTAGE 2
#define LDA 40                 // elements; 80B row stride, conflict-free LDSM
#define LDB 40

#define A_STAGE_BYTES (BM * LDA * 2)   // 10240
#define B_STAGE_BYTES (BN * LDB * 2)   // 10240
#define STAGE_BYTES (A_STAGE_BYTES + B_STAGE_BYTES)   // 20480
#define SMEM_TOTAL (NSTAGE * STAGE_BYTES)             // 40960 -> 4 CTAs/SM

// ---- scratch ----
__device__ __half g_xh[B_ROWS * P_DIM];
__device__ __half g_mh[C_PAD * P_DIM];
__device__ float g_fx[B_ROWS];     // 2 * r_b
__device__ float g_xsq[B_ROWS];
__device__ float g_msq[C_PAD];

// ======================= PTX helpers =======================
__device__ __forceinline__ uint32_t smem_u32(const void* p) {
    uint32_t a;
    asm("{ .reg .u64 t; cvta.to.shared.u64 t, %1; cvt.u32.u64 %0, t; }" : "=r"(a) : "l"(p));
    return a;
}
__device__ __forceinline__ void cp_async16(uint32_t dst, const void* src) {
    asm volatile("cp.async.cg.shared.global [%0], [%1], 16;" :: "r"(dst), "l"(src) : "memory");
}
__device__ __forceinline__ void cp_commit() {
    asm volatile("cp.async.commit_group;" ::: "memory");
}
__device__ __forceinline__ void cp_wait0() {
    asm volatile("cp.async.wait_group 0;" ::: "memory");
}
__device__ __forceinline__ void ldsm_x4(uint32_t& r0, uint32_t& r1, uint32_t& r2, uint32_t& r3,
                                        uint32_t addr) {
    asm volatile("ldmatrix.sync.aligned.m8n8.x4.shared.b16 {%0,%1,%2,%3}, [%4];"
                 : "=r"(r0), "=r"(r1), "=r"(r2), "=r"(r3) : "r"(addr));
}
// fp16 x fp16 -> fp16 accum
__device__ __forceinline__ void mma16816h(uint32_t c[2], const uint32_t a[4], const uint32_t b[2]) {
    asm volatile(
        "mma.sync.aligned.m16n8k16.row.col.f16.f16.f16.f16 "
        "{%0,%1}, {%2,%3,%4,%5}, {%6,%7}, {%0,%1};\n"
        : "+r"(c[0]), "+r"(c[1])
        : "r"(a[0]), "r"(a[1]), "r"(a[2]), "r"(a[3]), "r"(b[0]), "r"(b[1]));
}

// ======================= fused prep kernel =======================
// blocks [0,128): class rows (8/block). blocks [128,1152): x rows (8/block).
__global__ void prep_all(const float* __restrict__ x, const float* __restrict__ means) {
    const int wid = threadIdx.x >> 5, lane = threadIdx.x & 31;

    if (blockIdx.x < 128) {
        const int c = blockIdx.x * 8 + wid;
        float4 v[4];
        float ss = 0.0f;
        if (c < C_CLASSES) {
            const float4* src = (const float4*)(means + (size_t)c * P_DIM);
            #pragma unroll
            for (int i = 0; i < 4; i++) {
                v[i] = src[lane + i * 32];
                ss += v[i].x * v[i].x + v[i].y * v[i].y + v[i].z * v[i].z + v[i].w * v[i].w;
            }
        } else {
            #pragma unroll
            for (int i = 0; i < 4; i++) v[i] = make_float4(0.f, 0.f, 0.f, 0.f);
        }
        #pragma unroll
        for (int o = 16; o > 0; o >>= 1) ss += __shfl_xor_sync(0xffffffffu, ss, o);

        uint2* dst = (uint2*)(g_mh + (size_t)c * P_DIM);
        #pragma unroll
        for (int i = 0; i < 4; i++) {
            __half2 lo = __floats2half2_rn(v[i].x, v[i].y);
            __half2 hi = __floats2half2_rn(v[i].z, v[i].w);
            uint2 p; p.x = *(uint32_t*)&lo; p.y = *(uint32_t*)&hi;
            dst[lane + i * 32] = p;
        }
        if (lane == 0) g_msq[c] = ss;
    } else {
        const int b = (blockIdx.x - 128) * 8 + wid;
        float sc = 0.0f;
        {
            const float4* m0 = (const float4*)means;
            #pragma unroll
            for (int i = 0; i < 4; i++) {
                float4 m = m0[lane + i * 32];
                sc += m.x * m.x + m.y * m.y + m.z * m.z + m.w * m.w;
            }
            #pragma unroll
            for (int o = 16; o > 0; o >>= 1) sc += __shfl_xor_sync(0xffffffffu, sc, o);
            sc = sqrtf(sc);
        }

        const float4* src = (const float4*)(x + (size_t)b * P_DIM);
        float4 v[4];
        float ss = 0.0f;
        #pragma unroll
        for (int i = 0; i < 4; i++) {
            v[i] = src[lane + i * 32];
            ss += v[i].x * v[i].x + v[i].y * v[i].y + v[i].z * v[i].z + v[i].w * v[i].w;
        }
        #pragma unroll
        for (int o = 16; o > 0; o >>= 1) ss += __shfl_xor_sync(0xffffffffu, ss, o);

        uint2* dst = (uint2*)(g_xh + (size_t)b * P_DIM);
        #pragma unroll
        for (int i = 0; i < 4; i++) {
            __half2 lo = __floats2half2_rn(v[i].x, v[i].y);
            __half2 hi = __floats2half2_rn(v[i].z, v[i].w);
            uint2 p; p.x = *(uint32_t*)&lo; p.y = *(uint32_t*)&hi;
            dst[lane + i * 32] = p;
        }
        if (lane == 0) {
            float norm = sqrtf(ss);
            float r = sc / (norm + 1e-10f);
            g_fx[b] = 2.0f * r;
            float tn = norm * r;
            g_xsq[b] = tn * tn;
        }
    }
}

// ======================= fp16 HMMA GEMM, 4 CTAs/SM, single wave =======================
// grid (8, 64) = 512 CTAs over 592 slots -> one wave, no tail.
// 256 threads = 8 warps, 4(m) x 2(n), warptile 32x64, fp16 accumulators.
__global__ __launch_bounds__(256, 4) void gemm_logits(float* __restrict__ out) {
    extern __shared__ __align__(16) char smem_raw[];
    const uint32_t sbase = smem_u32(smem_raw);

    const int t = threadIdx.x;
    const int warp = t >> 5, lane = t & 31;
    const int wm = warp & 3;    // m-warp 0..3
    const int wn = warp >> 2;   // n-warp 0..1
    const int grp = lane >> 2, tid4 = lane & 3;
    const int bm = blockIdx.y * BM;
    const int bn = blockIdx.x * BN;

    // cp.async mapping: A = 512 16B-chunks, B = 512; 4 per thread.
    // chunk v: row = v>>2, colchunk = (v&3)*8 elements
    const __half* abase = g_xh + (size_t)bm * P_DIM;
    const __half* bbase = g_mh + (size_t)bn * P_DIM;
    uint32_t src_inv[4];
    uint32_t dsts[4];
    #pragma unroll
    for (int i = 0; i < 4; i++) {
        int v = t + i * 256;
        int v2 = v & 511;
        int r = v2 >> 2, cc = (v2 & 3) * 8;
        src_inv[i] = (uint32_t)(r * P_DIM + cc);
        dsts[i] = (uint32_t)(r * (i < 2 ? LDA : LDB) + cc) * 2 + (i < 2 ? 0u : (uint32_t)A_STAGE_BYTES);
    }

    // LDSM lane addressing
    const int lq = lane >> 3, lr = lane & 7;
    const uint32_t a_lane_off =
        (uint32_t)((wm * 32 + (lq & 1) * 8 + lr) * LDA + (lq >> 1) * 8) * 2;
    const uint32_t b_lane_off =
        A_STAGE_BYTES + (uint32_t)((wn * 64 + (lq >> 1) * 8 + lr) * LDB + (lq & 1) * 8) * 2;

    uint32_t acc[2][8][2];   // packed f16x2 accumulators
    #pragma unroll
    for (int mi = 0; mi < 2; mi++)
        #pragma unroll
        for (int ni = 0; ni < 8; ni++) {
            acc[mi][ni][0] = 0u;
            acc[mi][ni][1] = 0u;
        }

    auto issue_stage = [&](int c) {
        const uint32_t st = sbase + (c & 1) * STAGE_BYTES;
        const int koff = c * BK;
        #pragma unroll
        for (int i = 0; i < 4; i++)
            cp_async16(st + dsts[i], (i < 2 ? abase : bbase) + src_inv[i] + koff);
    };

    issue_stage(0); cp_commit();

    #pragma unroll 1
    for (int c = 0; c < NCHUNK; c++) {
        cp_wait0();          // stage c landed
        __syncthreads();     // all warps done with stage c-1 (same buffer c+1 writes)

        if (c + 1 < NCHUNK) { issue_stage(c + 1); cp_commit(); }

        const uint32_t st = sbase + (c & 1) * STAGE_BYTES;
        const uint32_t ast = st + a_lane_off;
        const uint32_t bst = st + b_lane_off;

        #pragma unroll
        for (int kk = 0; kk < BK; kk += 16) {
            uint32_t a[2][4];
            #pragma unroll
            for (int mi = 0; mi < 2; mi++)
                ldsm_x4(a[mi][0], a[mi][1], a[mi][2], a[mi][3],
                        ast + (uint32_t)(mi * 16 * LDA + kk) * 2);
            uint32_t b[8][2];
            #pragma unroll
            for (int ng = 0; ng < 4; ng++)
                ldsm_x4(b[ng * 2][0], b[ng * 2][1], b[ng * 2 + 1][0], b[ng * 2 + 1][1],
                        bst + (uint32_t)(ng * 16 * LDB + kk) * 2);
            #pragma unroll
            for (int mi = 0; mi < 2; mi++)
                #pragma unroll
                for (int ni = 0; ni < 8; ni++)
                    mma16816h(acc[mi][ni], a[mi], b[ni]);
        }
    }

    // ---- fused epilogue: out = fx_b * cross - xsq_b - msq_c ----
    #pragma unroll
    for (int mi = 0; mi < 2; mi++) {
        int row0 = bm + wm * 32 + mi * 16 + grp;
        float f0 = g_fx[row0], xs0 = g_xsq[row0];
        float f1 = g_fx[row0 + 8], xs1 = g_xsq[row0 + 8];
        #pragma unroll
        for (int ni = 0; ni < 8; ni++) {
            int col = bn + wn * 64 + ni * 8 + tid4 * 2;
            __half2 h0 = *(__half2*)&acc[mi][ni][0];
            __half2 h1 = *(__half2*)&acc[mi][ni][1];
            float2 c0 = __half22float2(h0);
            float2 c1 = __half22float2(h1);
            if (col < C_CLASSES) {
                float ms = g_msq[col];
                out[(size_t)row0 * C_CLASSES + col]       = f0 * c0.x - xs0 - ms;
                out[(size_t)(row0 + 8) * C_CLASSES + col] = f1 * c1.x - xs1 - ms;
            }
            if (col + 1 < C_CLASSES) {
                float ms = g_msq[col + 1];
                out[(size_t)row0 * C_CLASSES + col + 1]       = f0 * c0.y - xs0 - ms;
                out[(size_t)(row0 + 8) * C_CLASSES + col + 1] = f1 * c1.y - xs1 - ms;
            }
        }
    }
}

extern "C" void kernel_launch(void* const* d_in, const int* in_sizes, int n_in,
                              void* d_out, int out_size) {
    const float* x = (const float*)d_in[0];      // (8192, 512)
    const float* means = (const float*)d_in[1];  // (1000, 512)
    float* out = (float*)d_out;                  // (8192, 1000)
    (void)in_sizes; (void)n_in; (void)out_size;

    static int smem_set = 0;
    if (!smem_set) {
        cudaFuncSetAttribute(gemm_logits, cudaFuncAttributeMaxDynamicSharedMemorySize, SMEM_TOTAL);
        smem_set = 1;
    }

    prep_all<<<128 + B_ROWS / 8, 256>>>(x, means);
    dim3 grid(C_PAD / BN, B_ROWS / BM);
    gemm_logits<<<grid, 256, SMEM_TOTAL>>>(out);
}

// round 13
// speedup vs baseline: 1.3025x; 1.0413x over previous
#include <cuda_runtime.h>
#include <cuda_fp16.h>
#include <cstdint>

#define B_ROWS 8192
#define P_DIM 512
#define C_CLASSES 1000
#define C_PAD 1024

#define BM 128
#define BN 128
#define BK 64
#define NCHUNK (P_DIM / BK)   // 8
#define NSTAGE 2
#define LDA 72                 // elements; 144B row stride, conflict-free LDSM
#define LDB 72

#define A_STAGE_BYTES (BM * LDA * 2)   // 18432
#define B_STAGE_BYTES (BN * LDB * 2)   // 18432
#define STAGE_BYTES (A_STAGE_BYTES + B_STAGE_BYTES)   // 36864
#define SMEM_TOTAL (NSTAGE * STAGE_BYTES + 16)        // 73744 -> 3 CTAs/SM

#define N_TILES 512
#define GRID_CTAS 444          // 148 SMs * 3 CTAs

// ---- scratch ----
__device__ __half g_xh[B_ROWS * P_DIM];
__device__ __half g_mh[C_PAD * P_DIM];
__device__ float g_fx[B_ROWS];     // 2 * r_b
__device__ float g_xsq[B_ROWS];
__device__ float g_msq[C_PAD];
__device__ unsigned g_tile_ctr;

// ======================= PTX helpers =======================
__device__ __forceinline__ uint32_t smem_u32(const void* p) {
    uint32_t a;
    asm("{ .reg .u64 t; cvta.to.shared.u64 t, %1; cvt.u32.u64 %0, t; }" : "=r"(a) : "l"(p));
    return a;
}
__device__ __forceinline__ void cp_async16(uint32_t dst, const void* src) {
    asm volatile("cp.async.cg.shared.global [%0], [%1], 16;" :: "r"(dst), "l"(src) : "memory");
}
__device__ __forceinline__ void cp_commit() {
    asm volatile("cp.async.commit_group;" ::: "memory");
}
__device__ __forceinline__ void cp_wait0() {
    asm volatile("cp.async.wait_group 0;" ::: "memory");
}
__device__ __forceinline__ void ldsm_x4(uint32_t& r0, uint32_t& r1, uint32_t& r2, uint32_t& r3,
                                        uint32_t addr) {
    asm volatile("ldmatrix.sync.aligned.m8n8.x4.shared.b16 {%0,%1,%2,%3}, [%4];"
                 : "=r"(r0), "=r"(r1), "=r"(r2), "=r"(r3) : "r"(addr));
}
// fp16 x fp16 -> fp16 accum
__device__ __forceinline__ void mma16816h(uint32_t c[2], const uint32_t a[4], const uint32_t b[2]) {
    asm volatile(
        "mma.sync.aligned.m16n8k16.row.col.f16.f16.f16.f16 "
        "{%0,%1}, {%2,%3,%4,%5}, {%6,%7}, {%0,%1};\n"
        : "+r"(c[0]), "+r"(c[1])
        : "r"(a[0]), "r"(a[1]), "r"(a[2]), "r"(a[3]), "r"(b[0]), "r"(b[1]));
}

// ======================= fused prep kernel =======================
// blocks [0,128): class rows (8/block). blocks [128,1152): x rows (8/block).
__global__ void prep_all(const float* __restrict__ x, const float* __restrict__ means) {
    const int wid = threadIdx.x >> 5, lane = threadIdx.x & 31;
    if (blockIdx.x == 0 && threadIdx.x == 0) g_tile_ctr = 0;   // reset stealer

    if (blockIdx.x < 128) {
        const int c = blockIdx.x * 8 + wid;
        float4 v[4];
        float ss = 0.0f;
        if (c < C_CLASSES) {
            const float4* src = (const float4*)(means + (size_t)c * P_DIM);
            #pragma unroll
            for (int i = 0; i < 4; i++) {
                v[i] = src[lane + i * 32];
                ss += v[i].x * v[i].x + v[i].y * v[i].y + v[i].z * v[i].z + v[i].w * v[i].w;
            }
        } else {
            #pragma unroll
            for (int i = 0; i < 4; i++) v[i] = make_float4(0.f, 0.f, 0.f, 0.f);
        }
        #pragma unroll
        for (int o = 16; o > 0; o >>= 1) ss += __shfl_xor_sync(0xffffffffu, ss, o);

        uint2* dst = (uint2*)(g_mh + (size_t)c * P_DIM);
        #pragma unroll
        for (int i = 0; i < 4; i++) {
            __half2 lo = __floats2half2_rn(v[i].x, v[i].y);
            __half2 hi = __floats2half2_rn(v[i].z, v[i].w);
            uint2 p; p.x = *(uint32_t*)&lo; p.y = *(uint32_t*)&hi;
            dst[lane + i * 32] = p;
        }
        if (lane == 0) g_msq[c] = ss;
    } else {
        const int b = (blockIdx.x - 128) * 8 + wid;
        float sc = 0.0f;
        {
            const float4* m0 = (const float4*)means;
            #pragma unroll
            for (int i = 0; i < 4; i++) {
                float4 m = m0[lane + i * 32];
                sc += m.x * m.x + m.y * m.y + m.z * m.z + m.w * m.w;
            }
            #pragma unroll
            for (int o = 16; o > 0; o >>= 1) sc += __shfl_xor_sync(0xffffffffu, sc, o);
            sc = sqrtf(sc);
        }

        const float4* src = (const float4*)(x + (size_t)b * P_DIM);
        float4 v[4];
        float ss = 0.0f;
        #pragma unroll
        for (int i = 0; i < 4; i++) {
            v[i] = src[lane + i * 32];
            ss += v[i].x * v[i].x + v[i].y * v[i].y + v[i].z * v[i].z + v[i].w * v[i].w;
        }
        #pragma unroll
        for (int o = 16; o > 0; o >>= 1) ss += __shfl_xor_sync(0xffffffffu, ss, o);

        uint2* dst = (uint2*)(g_xh + (size_t)b * P_DIM);
        #pragma unroll
        for (int i = 0; i < 4; i++) {
            __half2 lo = __floats2half2_rn(v[i].x, v[i].y);
            __half2 hi = __floats2half2_rn(v[i].z, v[i].w);
            uint2 p; p.x = *(uint32_t*)&lo; p.y = *(uint32_t*)&hi;
            dst[lane + i * 32] = p;
        }
        if (lane == 0) {
            float norm = sqrtf(ss);
            float r = sc / (norm + 1e-10f);
            g_fx[b] = 2.0f * r;
            float tn = norm * r;
            g_xsq[b] = tn * tn;
        }
    }
}

// ======================= persistent fp16 HMMA GEMM, 3 CTAs/SM =======================
// 444 persistent CTAs steal 512 tiles. 256 threads = 8 warps, 4(m) x 2(n), warptile 32x64.
// BK=64, 2 stages, ONE sync per chunk.
__global__ __launch_bounds__(256, 3) void gemm_logits(float* __restrict__ out) {
    extern __shared__ __align__(16) char smem_raw[];
    const uint32_t sbase = smem_u32(smem_raw);
    unsigned* tile_bcast = (unsigned*)(smem_raw + NSTAGE * STAGE_BYTES);

    const int t = threadIdx.x;
    const int warp = t >> 5, lane = t & 31;
    const int wm = warp & 3;    // m-warp 0..3
    const int wn = warp >> 2;   // n-warp 0..1
    const int grp = lane >> 2, tid4 = lane & 3;

    // tile-invariant cp.async mapping: A = 1024 16B-chunks, B = 1024; 8 per thread.
    uint32_t src_inv[8];
    uint32_t dsts[8];
    #pragma unroll
    for (int i = 0; i < 8; i++) {
        int v = t + i * 256;
        int v2 = v & 1023;
        int r = v2 >> 3, cc = (v2 & 7) * 8;
        src_inv[i] = (uint32_t)(r * P_DIM + cc);
        dsts[i] = (uint32_t)(r * (i < 4 ? LDA : LDB) + cc) * 2 + (i < 4 ? 0u : (uint32_t)A_STAGE_BYTES);
    }

    // LDSM lane addressing
    const int lq = lane >> 3, lr = lane & 7;
    const uint32_t a_lane_off =
        (uint32_t)((wm * 32 + (lq & 1) * 8 + lr) * LDA + (lq >> 1) * 8) * 2;
    const uint32_t b_lane_off =
        A_STAGE_BYTES + (uint32_t)((wn * 64 + (lq >> 1) * 8 + lr) * LDB + (lq & 1) * 8) * 2;

    for (;;) {
        if (t == 0) *tile_bcast = atomicAdd(&g_tile_ctr, 1u);
        __syncthreads();     // broadcast + guards buffer reuse across tiles
        const unsigned tile = *tile_bcast;
        if (tile >= N_TILES) break;

        const int bm = (int)(tile >> 3) * BM;
        const int bn = (int)(tile & 7) * BN;
        const __half* abase = g_xh + (size_t)bm * P_DIM;
        const __half* bbase = g_mh + (size_t)bn * P_DIM;

        uint32_t acc[2][8][2];
        #pragma unroll
        for (int mi = 0; mi < 2; mi++)
            #pragma unroll
            for (int ni = 0; ni < 8; ni++) {
                acc[mi][ni][0] = 0u;
                acc[mi][ni][1] = 0u;
            }

        auto issue_stage = [&](int c) {
            const uint32_t st = sbase + (c & 1) * STAGE_BYTES;
            const int koff = c * BK;
            #pragma unroll
            for (int i = 0; i < 8; i++)
                cp_async16(st + dsts[i], (i < 4 ? abase : bbase) + src_inv[i] + koff);
        };

        issue_stage(0); cp_commit();

        #pragma unroll 1
        for (int c = 0; c < NCHUNK; c++) {
            cp_wait0();          // own stage-c copies landed
            __syncthreads();     // everyone's copies landed; chunk c-1 reads done

            if (c + 1 < NCHUNK) { issue_stage(c + 1); cp_commit(); }

            const uint32_t st = sbase + (c & 1) * STAGE_BYTES;
            const uint32_t ast = st + a_lane_off;
            const uint32_t bst = st + b_lane_off;

            #pragma unroll
            for (int kk = 0; kk < BK; kk += 16) {
                uint32_t a[2][4];
                #pragma unroll
                for (int mi = 0; mi < 2; mi++)
                    ldsm_x4(a[mi][0], a[mi][1], a[mi][2], a[mi][3],
                            ast + (uint32_t)(mi * 16 * LDA + kk) * 2);
                uint32_t b[8][2];
                #pragma unroll
                for (int ng = 0; ng < 4; ng++)
                    ldsm_x4(b[ng * 2][0], b[ng * 2][1], b[ng * 2 + 1][0], b[ng * 2 + 1][1],
                            bst + (uint32_t)(ng * 16 * LDB + kk) * 2);
                #pragma unroll
                for (int mi = 0; mi < 2; mi++)
                    #pragma unroll
                    for (int ni = 0; ni < 8; ni++)
                        mma16816h(acc[mi][ni], a[mi], b[ni]);
            }
        }

        // ---- fused epilogue: out = fx_b * cross - xsq_b - msq_c ----
        #pragma unroll
        for (int mi = 0; mi < 2; mi++) {
            int row0 = bm + wm * 32 + mi * 16 + grp;
            float f0 = g_fx[row0], xs0 = g_xsq[row0];
            float f1 = g_fx[row0 + 8], xs1 = g_xsq[row0 + 8];
            #pragma unroll
            for (int ni = 0; ni < 8; ni++) {
                int col = bn + wn * 64 + ni * 8 + tid4 * 2;
                __half2 h0 = *(__half2*)&acc[mi][ni][0];
                __half2 h1 = *(__half2*)&acc[mi][ni][1];
                float2 c0 = __half22float2(h0);
                float2 c1 = __half22float2(h1);
                if (col < C_CLASSES) {
                    float ms = g_msq[col];
                    out[(size_t)row0 * C_CLASSES + col]       = f0 * c0.x - xs0 - ms;
                    out[(size_t)(row0 + 8) * C_CLASSES + col] = f1 * c1.x - xs1 - ms;
                }
                if (col + 1 < C_CLASSES) {
                    float ms = g_msq[col + 1];
                    out[(size_t)row0 * C_CLASSES + col + 1]       = f0 * c0.y - xs0 - ms;
                    out[(size_t)(row0 + 8) * C_CLASSES + col + 1] = f1 * c1.y - xs1 - ms;
                }
            }
        }
    }
}

extern "C" void kernel_launch(void* const* d_in, const int* in_sizes, int n_in,
                              void* d_out, int out_size) {
    const float* x = (const float*)d_in[0];      // (8192, 512)
    const float* means = (const float*)d_in[1];  // (1000, 512)
    float* out = (float*)d_out;                  // (8192, 1000)
    (void)in_sizes; (void)n_in; (void)out_size;

    static int smem_set = 0;
    if (!smem_set) {
        cudaFuncSetAttribute(gemm_logits, cudaFuncAttributeMaxDynamicSharedMemorySize, SMEM_TOTAL);
        smem_set = 1;
    }

    prep_all<<<128 + B_ROWS / 8, 256>>>(x, means);
    gemm_logits<<<GRID_CTAS, 256, SMEM_TOTAL>>>(out);
}